// round 6
// baseline (speedup 1.0000x reference)
#include <cuda_runtime.h>
#include <stdint.h>

// Voxelize_52321291600272
// B=8, NV=2048, NF=512, grid 96^3. Output float32 alpha in {0,1}.
// alpha[b,x,y,z] = 1 iff voxel center inside ANY tetrahedron (union), so a
// scatter of 1.0f per inside (tet,point) pair is exact and race-free.
//
// Facets dtype is int64 in the reference; the harness may materialize it as
// int32 or int64 on device. We detect which on-device: for int64 (LE) data,
// all odd 32-bit words (high words of small nonneg indices) are zero.

#define VWI 96
#define NVI 2048
#define NFI 512
#define BI  8

__device__ int g_facets_is_i32;

__global__ void detect_facets_dtype(const int* __restrict__ w)
{
    __shared__ int found;
    if (threadIdx.x == 0) found = 0;
    __syncthreads();
    // Scan odd words of the first 16384 int32 words (guaranteed in-bounds:
    // the buffer holds >= 16384 elements of >= 4 bytes each).
    for (int i = 2 * threadIdx.x + 1; i < 16384; i += 2 * blockDim.x) {
        if (w[i] != 0) found = 1;   // benign race, all write 1
    }
    __syncthreads();
    if (threadIdx.x == 0) g_facets_is_i32 = found;
}

__global__ __launch_bounds__(128)
void voxelize_scatter_kernel(const float* __restrict__ vertices,
                             const int* __restrict__ facets_raw,
                             float* __restrict__ out)
{
    const int bf = blockIdx.x;
    const int b = bf / NFI;
    const int f = bf % NFI;
    const int is32 = g_facets_is_i32;

    const float* vb = vertices + (long long)b * NVI * 3;

    float vx[4], vy[4], vz[4];
#pragma unroll
    for (int j = 0; j < 4; j++) {
        int vi;
        if (is32) {
            vi = facets_raw[((long long)b * NFI + f) * 4 + j];
        } else {
            // int64 little-endian: take the low word
            vi = facets_raw[(((long long)b * NFI + f) * 4 + j) * 2];
        }
        vx[j] = vb[vi * 3 + 0];
        vy[j] = vb[vi * 3 + 1];
        vz[j] = vb[vi * 3 + 2];
    }

    const float v3x = vx[3], v3y = vy[3], v3z = vz[3];
    // Edge matrix columns e_j = vert_j - v3; reference names:
    const float a  = vx[0] - v3x, bb = vx[1] - v3x, c  = vx[2] - v3x;
    const float d  = vy[0] - v3y, e  = vy[1] - v3y, ff = vy[2] - v3y;
    const float g  = vz[0] - v3z, h  = vz[1] - v3z, i_ = vz[2] - v3z;

    // Adjugate rows (reference formulas)
    const float A00 = e * i_ - ff * h,  A01 = c * h - bb * i_, A02 = bb * ff - c * e;
    const float A10 = ff * g - d * i_,  A11 = a * i_ - c * g,  A12 = c * d - a * ff;
    const float A20 = d * h - e * g,    A21 = bb * g - a * h,  A22 = a * e - bb * d;
    const float det = a * (e * i_ - ff * h) - bb * (d * i_ - ff * g) + c * (d * h - e * g);

    // AABB of the tet
    float xmn = fminf(fminf(vx[0], vx[1]), fminf(vx[2], vx[3]));
    float xmx = fmaxf(fmaxf(vx[0], vx[1]), fmaxf(vx[2], vx[3]));
    float ymn = fminf(fminf(vy[0], vy[1]), fminf(vy[2], vy[3]));
    float ymx = fmaxf(fmaxf(vy[0], vy[1]), fmaxf(vy[2], vy[3]));
    float zmn = fminf(fminf(vz[0], vz[1]), fminf(vz[2], vz[3]));
    float zmx = fmaxf(fmaxf(vz[0], vz[1]), fmaxf(vz[2], vz[3]));

    // Coordinate of index k: (2k+1-96)/96  ->  k(z) = (96 z + 95)/2
    // Conservative index ranges (expanded +-1, clamped to [0,95]).
    int xlo = max(0,  (int)ceilf ((96.f * xmn + 95.f) * 0.5f) - 1);
    int xhi = min(95, (int)floorf((96.f * xmx + 95.f) * 0.5f) + 1);
    int ylo = max(0,  (int)ceilf ((96.f * ymn + 95.f) * 0.5f) - 1);
    int yhi = min(95, (int)floorf((96.f * ymx + 95.f) * 0.5f) + 1);
    int zloi = max(0,  (int)ceilf ((96.f * zmn + 95.f) * 0.5f) - 1);
    int zhii = min(95, (int)floorf((96.f * zmx + 95.f) * 0.5f) + 1);
    if (xlo > xhi || ylo > yhi || zloi > zhii) return;

    const int ny = yhi - ylo + 1;
    const int ncol = (xhi - xlo + 1) * ny;

    // Bounds for n_r = lam_r * det:  det>0: 0<=n<=det ; det<0: det<=n<=0
    const float Lb = fminf(0.f, det);
    const float Ub = fmaxf(0.f, det);
    const float tol = 1e-5f;
    const float adet = fabsf(det);

    for (int col = threadIdx.x; col < ncol; col += blockDim.x) {
        const int x = xlo + col / ny;
        const int y = ylo + col % ny;
        const float px = (float)(2 * x + 1 - VWI) / 96.f;
        const float py = (float)(2 * y + 1 - VWI) / 96.f;
        const float dx = px - v3x;
        const float dy = py - v3y;

        // n_r(zc) = C_r + S_r * zc  (zc = z coordinate)
        const float C1 = A00 * dx + A01 * dy - A02 * v3z;  const float S1 = A02;
        const float C2 = A10 * dx + A11 * dy - A12 * v3z;  const float S2 = A12;
        const float C3 = A20 * dx + A21 * dy - A22 * v3z;  const float S3 = A22;
        const float C4 = det - C1 - C2 - C3;               const float S4 = -(S1 + S2 + S3);

        // Cancellation-aware error scales (magnitudes of contributing terms)
        const float M1 = fabsf(A00 * dx) + fabsf(A01 * dy) + fabsf(A02 * v3z);
        const float M2 = fabsf(A10 * dx) + fabsf(A11 * dy) + fabsf(A12 * v3z);
        const float M3 = fabsf(A20 * dx) + fabsf(A21 * dy) + fabsf(A22 * v3z);
        const float M4 = M1 + M2 + M3 + adet;

        float zlo = -2.f, zhi = 2.f;
        bool empty = false;
        const float Cs[4] = {C1, C2, C3, C4};
        const float Ss[4] = {S1, S2, S3, S4};
        const float Ms[4] = {M1, M2, M3, M4};
#pragma unroll
        for (int r = 0; r < 4; r++) {
            const float Cr = Cs[r], Sr = Ss[r];
            const float m = tol * (Ms[r] + adet) + 1e-30f;
            if (fabsf(Sr) * 4.f <= m) {
                // z-independent within tolerance: either unrestricted or empty
                if (Cr < Lb - m || Cr > Ub + m) empty = true;
            } else {
                const float inv = 1.f / Sr;
                const float za = (Lb - Cr) * inv;
                const float zb = (Ub - Cr) * inv;
                const float sl = m * fabsf(inv);
                zlo = fmaxf(zlo, fminf(za, zb) - sl);
                zhi = fminf(zhi, fmaxf(za, zb) + sl);
            }
        }
        if (empty || zlo > zhi) continue;

        int klo = max(zloi, (int)ceilf ((96.f * zlo + 95.f) * 0.5f) - 1);
        int khi = min(zhii, (int)floorf((96.f * zhi + 95.f) * 0.5f) + 1);
        if (klo > khi) continue;

        float* orow = out + ((((long long)b * VWI + x) * VWI + y) * VWI);

        for (int k = klo; k <= khi; k++) {
            const float pz = (float)(2 * k + 1 - VWI) / 96.f;
            const float dz = pz - v3z;
            // Exact test, same formula/ordering as the reference:
            const float n1 = fmaf(A02, dz, fmaf(A01, dy, A00 * dx));
            const float n2 = fmaf(A12, dz, fmaf(A11, dy, A10 * dx));
            const float n3 = fmaf(A22, dz, fmaf(A21, dy, A20 * dx));
            const float l1 = n1 / det;
            const float l2 = n2 / det;
            const float l3 = n3 / det;
            const float l4 = 1.0f - (l1 + l2 + l3);
            const bool inside =
                (l1 >= 0.f) & (l1 <= 1.f) &
                (l2 >= 0.f) & (l2 <= 1.f) &
                (l3 >= 0.f) & (l3 <= 1.f) &
                (l4 >= 0.f) & (l4 <= 1.f);
            if (inside) orow[k] = 1.0f;
        }
    }
}

extern "C" void kernel_launch(void* const* d_in, const int* in_sizes, int n_in,
                              void* d_out, int out_size)
{
    const float* vertices = (const float*)d_in[0];   // (8, 2048, 3) f32
    const int* facets_raw = (const int*)d_in[1];     // (8, 512, 4) i32 or i64 (detected)
    float* out = (float*)d_out;                      // (8, 96, 96, 96) f32

    detect_facets_dtype<<<1, 256>>>(facets_raw);

    // Output is poisoned before timing; zero it (union scatter only writes 1s).
    cudaMemsetAsync(d_out, 0, (size_t)out_size * sizeof(float));

    voxelize_scatter_kernel<<<BI * NFI, 128>>>(vertices, facets_raw, out);
}

// round 11
// speedup vs baseline: 2.5935x; 2.5935x over previous
#include <cuda_runtime.h>
#include <stdint.h>

// Voxelize_52321291600272
// B=8, NV=2048, NF=512, grid 96^3. Output float32 alpha in {0,1}.
// alpha[b,x,y,z] = 1 iff voxel center inside ANY tetrahedron (union):
// scatter of 1.0f per inside (tet,point) pair is exact and race-free.

#define VWI 96
#define NVI 2048
#define NFI 512
#define BI  8
#define SPLIT 8

__device__ int g_facets_is_i32;

__global__ void detect_facets_dtype(const int* __restrict__ w)
{
    __shared__ int found;
    if (threadIdx.x == 0) found = 0;
    __syncthreads();
    // int64 LE data => every odd 32-bit word (high word of small index) is 0.
    for (int i = 2 * threadIdx.x + 1; i < 16384; i += 2 * blockDim.x) {
        if (w[i] != 0) found = 1;   // benign race
    }
    __syncthreads();
    if (threadIdx.x == 0) g_facets_is_i32 = found;
}

__global__ __launch_bounds__(128)
void voxelize_scatter_kernel(const float* __restrict__ vertices,
                             const int* __restrict__ facets_raw,
                             float* __restrict__ out)
{
    __shared__ float gc[VWI];   // grid coordinate table (bit-identical expr)
    if (threadIdx.x < VWI)
        gc[threadIdx.x] = (float)(2 * (int)threadIdx.x + 1 - VWI) / 96.f;  // SIGNED!
    __syncthreads();

    const int bfs = blockIdx.x;
    const int sub = bfs % SPLIT;
    const int bf  = bfs / SPLIT;
    const int b = bf / NFI;
    const int f = bf % NFI;
    const int is32 = g_facets_is_i32;

    const float* vb = vertices + (long long)b * NVI * 3;

    float vx[4], vy[4], vz[4];
#pragma unroll
    for (int j = 0; j < 4; j++) {
        long long base = ((long long)b * NFI + f) * 4 + j;
        int vi = is32 ? facets_raw[base] : facets_raw[base * 2];
        vx[j] = vb[vi * 3 + 0];
        vy[j] = vb[vi * 3 + 1];
        vz[j] = vb[vi * 3 + 2];
    }

    const float v3x = vx[3], v3y = vy[3], v3z = vz[3];
    const float a  = vx[0] - v3x, bb = vx[1] - v3x, c  = vx[2] - v3x;
    const float d  = vy[0] - v3y, e  = vy[1] - v3y, ff = vy[2] - v3y;
    const float g  = vz[0] - v3z, h  = vz[1] - v3z, i_ = vz[2] - v3z;

    // Adjugate rows (reference formulas)
    const float A00 = e * i_ - ff * h,  A01 = c * h - bb * i_, A02 = bb * ff - c * e;
    const float A10 = ff * g - d * i_,  A11 = a * i_ - c * g,  A12 = c * d - a * ff;
    const float A20 = d * h - e * g,    A21 = bb * g - a * h,  A22 = a * e - bb * d;
    const float det = a * (e * i_ - ff * h) - bb * (d * i_ - ff * g) + c * (d * h - e * g);
    const float inv_det = 1.0f / det;
    const float adet = fabsf(det);

    // AABB
    float xmn = fminf(fminf(vx[0], vx[1]), fminf(vx[2], vx[3]));
    float xmx = fmaxf(fmaxf(vx[0], vx[1]), fmaxf(vx[2], vx[3]));
    float ymn = fminf(fminf(vy[0], vy[1]), fminf(vy[2], vy[3]));
    float ymx = fmaxf(fmaxf(vy[0], vy[1]), fmaxf(vy[2], vy[3]));
    float zmn = fminf(fminf(vz[0], vz[1]), fminf(vz[2], vz[3]));
    float zmx = fmaxf(fmaxf(vz[0], vz[1]), fmaxf(vz[2], vz[3]));

    // k(z) = (96 z + 95)/2, ranges expanded +-1, clamped.
    int xlo = max(0,  (int)ceilf ((96.f * xmn + 95.f) * 0.5f) - 1);
    int xhi = min(95, (int)floorf((96.f * xmx + 95.f) * 0.5f) + 1);
    int ylo = max(0,  (int)ceilf ((96.f * ymn + 95.f) * 0.5f) - 1);
    int yhi = min(95, (int)floorf((96.f * ymx + 95.f) * 0.5f) + 1);
    int zloi = max(0,  (int)ceilf ((96.f * zmn + 95.f) * 0.5f) - 1);
    int zhii = min(95, (int)floorf((96.f * zmx + 95.f) * 0.5f) + 1);
    if (xlo > xhi || ylo > yhi || zloi > zhii) return;

    const int ny = yhi - ylo + 1;
    const int ncol = (xhi - xlo + 1) * ny;

    // This sub-block's column slice
    const int c0 = (int)(((long long)ncol * sub) / SPLIT);
    const int c1 = (int)(((long long)ncol * (sub + 1)) / SPLIT);

    // magic division by ny (col < 2^14, ny <= 96: error term col/2^22 < 1/ny, safe)
    const unsigned magic = (1u << 22) / (unsigned)ny + 1u;

    // Per-tet interval constants. n_r(z) = C_r + S_r*z must lie in [Lb,Ub].
    const float Lb = fminf(0.f, det);
    const float Ub = fmaxf(0.f, det);
    const float tol = 1e-5f;

    const float S1 = A02, S2 = A12, S3 = A22, S4 = -(S1 + S2 + S3);
    const float inv1 = 1.f / S1, inv2 = 1.f / S2, inv3 = 1.f / S3, inv4 = 1.f / S4;
    // Conservative per-tet error scales (|dx|,|dy|,|v3z| <= 2)
    const float M1 = 2.f * (fabsf(A00) + fabsf(A01) + fabsf(A02));
    const float M2 = 2.f * (fabsf(A10) + fabsf(A11) + fabsf(A12));
    const float M3 = 2.f * (fabsf(A20) + fabsf(A21) + fabsf(A22));
    const float M4 = M1 + M2 + M3 + adet;
    const float sl1 = (tol * (M1 + 2.f * adet)) * fabsf(inv1);
    const float sl2 = (tol * (M2 + 2.f * adet)) * fabsf(inv2);
    const float sl3 = (tol * (M3 + 2.f * adet)) * fabsf(inv3);
    const float sl4 = (tol * (M4 + 2.f * adet)) * fabsf(inv4);

    // Column-constant parts of C_r
    const float K1 = -A02 * v3z, K2 = -A12 * v3z, K3 = -A22 * v3z;

    for (int col = c0 + threadIdx.x; col < c1; col += blockDim.x) {
        const int q = (int)(((unsigned)col * magic) >> 22);
        const int x = xlo + q;
        const int y = ylo + (col - q * ny);
        const float dx = gc[x] - v3x;
        const float dy = gc[y] - v3y;

        const float C1 = fmaf(A01, dy, fmaf(A00, dx, K1));
        const float C2 = fmaf(A11, dy, fmaf(A10, dx, K2));
        const float C3 = fmaf(A21, dy, fmaf(A20, dx, K3));
        const float C4 = det - C1 - C2 - C3;

        float zlo = -2.f, zhi = 2.f;
        {   // NaN/inf from degenerate S fall through fminf/fmaxf conservatively
            float za, zb;
            za = (Lb - C1) * inv1; zb = (Ub - C1) * inv1;
            zlo = fmaxf(zlo, fminf(za, zb) - sl1); zhi = fminf(zhi, fmaxf(za, zb) + sl1);
            za = (Lb - C2) * inv2; zb = (Ub - C2) * inv2;
            zlo = fmaxf(zlo, fminf(za, zb) - sl2); zhi = fminf(zhi, fmaxf(za, zb) + sl2);
            za = (Lb - C3) * inv3; zb = (Ub - C3) * inv3;
            zlo = fmaxf(zlo, fminf(za, zb) - sl3); zhi = fminf(zhi, fmaxf(za, zb) + sl3);
            za = (Lb - C4) * inv4; zb = (Ub - C4) * inv4;
            zlo = fmaxf(zlo, fminf(za, zb) - sl4); zhi = fminf(zhi, fmaxf(za, zb) + sl4);
        }
        if (!(zlo <= zhi)) continue;

        int klo = max(zloi, (int)ceilf ((96.f * zlo + 95.f) * 0.5f) - 1);
        int khi = min(zhii, (int)floorf((96.f * zhi + 95.f) * 0.5f) + 1);
        if (klo > khi) continue;

        // Column-invariant bases (bit-identical hoist of inner fmaf)
        const float base1 = fmaf(A01, dy, A00 * dx);
        const float base2 = fmaf(A11, dy, A10 * dx);
        const float base3 = fmaf(A21, dy, A20 * dx);

        int kfirst = 127, klast = -1;
        for (int k = klo; k <= khi; k++) {
            const float dz = gc[k] - v3z;
            const float l1 = fmaf(A02, dz, base1) * inv_det;
            const float l2 = fmaf(A12, dz, base2) * inv_det;
            const float l3 = fmaf(A22, dz, base3) * inv_det;
            const float l4 = 1.0f - (l1 + l2 + l3);
            const float lmn = fminf(fminf(l1, l2), fminf(l3, l4));
            const float lmx = fmaxf(fmaxf(l1, l2), fmaxf(l3, l4));
            if (lmn >= 0.f && lmx <= 1.f) {
                kfirst = min(kfirst, k);
                klast = k;
            }
        }
        if (klast < 0) continue;

        // Inside set per column is a z-interval (convexity): run store, vectorized.
        float* orow = out + ((((long long)b * VWI + x) * VWI + y) * VWI);
        int k = kfirst;
        while (k <= klast && (k & 3)) orow[k++] = 1.0f;
        while (k + 3 <= klast) {
            *reinterpret_cast<float4*>(orow + k) = make_float4(1.f, 1.f, 1.f, 1.f);
            k += 4;
        }
        while (k <= klast) orow[k++] = 1.0f;
    }
}

extern "C" void kernel_launch(void* const* d_in, const int* in_sizes, int n_in,
                              void* d_out, int out_size)
{
    const float* vertices = (const float*)d_in[0];   // (8, 2048, 3) f32
    const int* facets_raw = (const int*)d_in[1];     // (8, 512, 4) i32/i64 (detected)
    float* out = (float*)d_out;                      // (8, 96, 96, 96) f32

    detect_facets_dtype<<<1, 256>>>(facets_raw);
    cudaMemsetAsync(d_out, 0, (size_t)out_size * sizeof(float));
    voxelize_scatter_kernel<<<BI * NFI * SPLIT, 128>>>(vertices, facets_raw, out);
}

// round 12
// speedup vs baseline: 2.6082x; 1.0057x over previous
#include <cuda_runtime.h>
#include <stdint.h>

// Voxelize_52321291600272
// B=8, NV=2048, NF=512, grid 96^3. Output float32 alpha in {0,1}.
// alpha[b,x,y,z] = 1 iff voxel center inside ANY tetrahedron (union):
// scatter of 1.0f per inside (tet,point) pair is exact and race-free.

#define VWI 96
#define NVI 2048
#define NFI 512
#define BI  8
#define SPLIT 8

__device__ int g_facets_is_i32;

__global__ void detect_facets_dtype(const int* __restrict__ w)
{
    __shared__ int found;
    if (threadIdx.x == 0) found = 0;
    __syncthreads();
    // int64 LE data => every odd 32-bit word (high word of small index) is 0.
    for (int i = 2 * threadIdx.x + 1; i < 16384; i += 2 * blockDim.x) {
        if (w[i] != 0) found = 1;   // benign race
    }
    __syncthreads();
    if (threadIdx.x == 0) g_facets_is_i32 = found;
}

__global__ __launch_bounds__(128)
void voxelize_scatter_kernel(const float* __restrict__ vertices,
                             const int* __restrict__ facets_raw,
                             float* __restrict__ out)
{
    __shared__ float gc[VWI];   // grid coordinate table (bit-identical expr)
    if (threadIdx.x < VWI)
        gc[threadIdx.x] = (float)(2 * (int)threadIdx.x + 1 - VWI) / 96.f;  // signed
    __syncthreads();

    const int bfs = blockIdx.x;
    const int sub = bfs % SPLIT;
    const int bf  = bfs / SPLIT;
    const int b = bf / NFI;
    const int f = bf % NFI;
    const int is32 = g_facets_is_i32;

    const float* vb = vertices + b * (NVI * 3);

    float vx[4], vy[4], vz[4];
#pragma unroll
    for (int j = 0; j < 4; j++) {
        int base = (b * NFI + f) * 4 + j;           // < 16384, 32-bit safe
        int vi = is32 ? facets_raw[base] : facets_raw[base * 2];
        vx[j] = vb[vi * 3 + 0];
        vy[j] = vb[vi * 3 + 1];
        vz[j] = vb[vi * 3 + 2];
    }

    const float v3x = vx[3], v3y = vy[3], v3z = vz[3];
    const float a  = vx[0] - v3x, bb = vx[1] - v3x, c  = vx[2] - v3x;
    const float d  = vy[0] - v3y, e  = vy[1] - v3y, ff = vy[2] - v3y;
    const float g  = vz[0] - v3z, h  = vz[1] - v3z, i_ = vz[2] - v3z;

    // Adjugate rows (reference formulas)
    const float A00 = e * i_ - ff * h,  A01 = c * h - bb * i_, A02 = bb * ff - c * e;
    const float A10 = ff * g - d * i_,  A11 = a * i_ - c * g,  A12 = c * d - a * ff;
    const float A20 = d * h - e * g,    A21 = bb * g - a * h,  A22 = a * e - bb * d;
    const float det = a * (e * i_ - ff * h) - bb * (d * i_ - ff * g) + c * (d * h - e * g);
    const float inv_det = 1.0f / det;
    const float adet = fabsf(det);

    // AABB
    float xmn = fminf(fminf(vx[0], vx[1]), fminf(vx[2], vx[3]));
    float xmx = fmaxf(fmaxf(vx[0], vx[1]), fmaxf(vx[2], vx[3]));
    float ymn = fminf(fminf(vy[0], vy[1]), fminf(vy[2], vy[3]));
    float ymx = fmaxf(fmaxf(vy[0], vy[1]), fmaxf(vy[2], vy[3]));
    float zmn = fminf(fminf(vz[0], vz[1]), fminf(vz[2], vz[3]));
    float zmx = fmaxf(fmaxf(vz[0], vz[1]), fmaxf(vz[2], vz[3]));

    // k(z) = (96 z + 95)/2, ranges expanded +-1, clamped.
    int xlo = max(0,  (int)ceilf ((96.f * xmn + 95.f) * 0.5f) - 1);
    int xhi = min(95, (int)floorf((96.f * xmx + 95.f) * 0.5f) + 1);
    int ylo = max(0,  (int)ceilf ((96.f * ymn + 95.f) * 0.5f) - 1);
    int yhi = min(95, (int)floorf((96.f * ymx + 95.f) * 0.5f) + 1);
    int zloi = max(0,  (int)ceilf ((96.f * zmn + 95.f) * 0.5f) - 1);
    int zhii = min(95, (int)floorf((96.f * zmx + 95.f) * 0.5f) + 1);
    if (xlo > xhi || ylo > yhi || zloi > zhii) return;

    const int ny = yhi - ylo + 1;
    const int ncol = (xhi - xlo + 1) * ny;

    // This sub-block's column slice (ncol*SPLIT < 2^17: 32-bit safe)
    const int c0 = (ncol * sub) / SPLIT;
    const int c1 = (ncol * (sub + 1)) / SPLIT;

    // magic division by ny (col < 2^14, ny <= 96)
    const unsigned magic = (1u << 22) / (unsigned)ny + 1u;

    // n_r(z) = C_r + S_r*z must lie in [Lb - m_r, Ub + m_r].
    const float Lb = fminf(0.f, det);
    const float Ub = fmaxf(0.f, det);
    const float tol = 1e-5f;

    const float S1 = A02, S2 = A12, S3 = A22, S4 = -(S1 + S2 + S3);
    const float inv1 = 1.f / S1, inv2 = 1.f / S2, inv3 = 1.f / S3, inv4 = 1.f / S4;
    // Conservative per-tet error scales (|dx|,|dy|,|v3z| <= 2)
    const float M1 = 2.f * (fabsf(A00) + fabsf(A01) + fabsf(A02));
    const float M2 = 2.f * (fabsf(A10) + fabsf(A11) + fabsf(A12));
    const float M3 = 2.f * (fabsf(A20) + fabsf(A21) + fabsf(A22));
    const float M4 = M1 + M2 + M3 + adet;
    const float m1 = tol * (M1 + 2.f * adet);
    const float m2 = tol * (M2 + 2.f * adet);
    const float m3 = tol * (M3 + 2.f * adet);
    const float m4 = tol * (M4 + 2.f * adet);

    // Pre-multiplied z-bound constants. Sign of inv picks which band edge maps
    // to the lower bound; fminf/fmaxf does the selection per tet. Degenerate
    // S (inv=+-inf): wrong-side candidates become NaN per column and are
    // dropped by the fmaxf/fminf trees (conservative; exact test decides).
    const float ZlP1 = fminf((Lb - m1) * inv1, (Ub + m1) * inv1);
    const float ZhP1 = fmaxf((Lb - m1) * inv1, (Ub + m1) * inv1);
    const float ZlP2 = fminf((Lb - m2) * inv2, (Ub + m2) * inv2);
    const float ZhP2 = fmaxf((Lb - m2) * inv2, (Ub + m2) * inv2);
    const float ZlP3 = fminf((Lb - m3) * inv3, (Ub + m3) * inv3);
    const float ZhP3 = fmaxf((Lb - m3) * inv3, (Ub + m3) * inv3);
    const float ZlP4 = fminf((Lb - m4) * inv4, (Ub + m4) * inv4);
    const float ZhP4 = fmaxf((Lb - m4) * inv4, (Ub + m4) * inv4);
    const float ninv1 = -inv1, ninv2 = -inv2, ninv3 = -inv3, ninv4 = -inv4;

    const int orow_base = (b * VWI + xlo) * (VWI * VWI);  // 32-bit safe (< 7.1M)

    for (int col = c0 + (int)threadIdx.x; col < c1; col += blockDim.x) {
        const int q = (int)(((unsigned)col * magic) >> 22);
        const int x = xlo + q;
        const int y = ylo + (col - q * ny);
        const float dx = gc[x] - v3x;
        const float dy = gc[y] - v3y;

        // Bit-exact inner-loop bases (reference op order for the z loop)
        const float base1 = fmaf(A01, dy, A00 * dx);
        const float base2 = fmaf(A11, dy, A10 * dx);
        const float base3 = fmaf(A21, dy, A20 * dx);
        // C_r = base_r - A_r2*v3z (1 ulp vs reference C; covered by slack m_r)
        const float C1 = fmaf(-A02, v3z, base1);
        const float C2 = fmaf(-A12, v3z, base2);
        const float C3 = fmaf(-A22, v3z, base3);
        const float C4 = det - C1 - C2 - C3;

        // One FMA per z-bound candidate
        const float zl1 = fmaf(C1, ninv1, ZlP1), zh1 = fmaf(C1, ninv1, ZhP1);
        const float zl2 = fmaf(C2, ninv2, ZlP2), zh2 = fmaf(C2, ninv2, ZhP2);
        const float zl3 = fmaf(C3, ninv3, ZlP3), zh3 = fmaf(C3, ninv3, ZhP3);
        const float zl4 = fmaf(C4, ninv4, ZlP4), zh4 = fmaf(C4, ninv4, ZhP4);
        const float zlo = fmaxf(fmaxf(fmaxf(zl1, zl2), fmaxf(zl3, zl4)), -2.f);
        const float zhi = fminf(fminf(fminf(zh1, zh2), fminf(zh3, zh4)),  2.f);
        if (!(zlo <= zhi)) continue;

        int klo = max(zloi, (int)ceilf ((96.f * zlo + 95.f) * 0.5f) - 1);
        int khi = min(zhii, (int)floorf((96.f * zhi + 95.f) * 0.5f) + 1);
        if (klo > khi) continue;

        int kfirst = 127, klast = -1;
        for (int k = klo; k <= khi; k++) {
            const float dz = gc[k] - v3z;
            // Exact test, same formula/ordering as the reference:
            const float l1 = fmaf(A02, dz, base1) * inv_det;
            const float l2 = fmaf(A12, dz, base2) * inv_det;
            const float l3 = fmaf(A22, dz, base3) * inv_det;
            const float l4 = 1.0f - (l1 + l2 + l3);
            const float lmn = fminf(fminf(l1, l2), fminf(l3, l4));
            const float lmx = fmaxf(fmaxf(l1, l2), fmaxf(l3, l4));
            if (lmn >= 0.f && lmx <= 1.f) {
                kfirst = min(kfirst, k);
                klast = k;
            }
        }
        if (klast < 0) continue;

        // Inside set per column is a z-interval (convexity): run store, vectorized.
        float* orow = out + (orow_base + (q * VWI + (y - ylo) + ylo) * VWI
                             + (q * 0));  // == out + ((b*96+x)*96+y)*96
        // (simplified below for clarity)
        orow = out + (((b * VWI + x) * VWI + y) * VWI);
        int k = kfirst;
        while (k <= klast && (k & 3)) orow[k++] = 1.0f;
        while (k + 3 <= klast) {
            *reinterpret_cast<float4*>(orow + k) = make_float4(1.f, 1.f, 1.f, 1.f);
            k += 4;
        }
        while (k <= klast) orow[k++] = 1.0f;
    }
}

extern "C" void kernel_launch(void* const* d_in, const int* in_sizes, int n_in,
                              void* d_out, int out_size)
{
    const float* vertices = (const float*)d_in[0];   // (8, 2048, 3) f32
    const int* facets_raw = (const int*)d_in[1];     // (8, 512, 4) i32/i64 (detected)
    float* out = (float*)d_out;                      // (8, 96, 96, 96) f32

    detect_facets_dtype<<<1, 256>>>(facets_raw);
    cudaMemsetAsync(d_out, 0, (size_t)out_size * sizeof(float));
    voxelize_scatter_kernel<<<BI * NFI * SPLIT, 128>>>(vertices, facets_raw, out);
}

// round 14
// speedup vs baseline: 3.9508x; 1.5147x over previous
#include <cuda_runtime.h>
#include <stdint.h>

// Voxelize_52321291600272
// B=8, NV=2048, NF=512, grid 96^3. Output float32 alpha in {0,1}.
// alpha[b,x,y,z] = 1 iff voxel center inside ANY tetrahedron (union):
// scatter of 1.0f per inside (tet,point) pair is exact and race-free.
//
// Per column: outer z-interval (band +- slack) brackets candidates; inner
// z-interval (band -+ slack) is GUARANTEED inside (slack >> fp rounding of the
// reference's computed test). Only frontier voxels get the exact test.

#define VWI 96
#define NVI 2048
#define NFI 512
#define BI  8
#define SPLIT 8

__device__ int g_facets_is_i32;

__global__ void detect_facets_dtype(const int* __restrict__ w)
{
    __shared__ int found;
    if (threadIdx.x == 0) found = 0;
    __syncthreads();
    // int64 LE data => every odd 32-bit word (high word of small index) is 0.
    for (int i = 2 * threadIdx.x + 1; i < 16384; i += 2 * blockDim.x) {
        if (w[i] != 0) found = 1;   // benign race
    }
    __syncthreads();
    if (threadIdx.x == 0) g_facets_is_i32 = found;
}

__global__ __launch_bounds__(128)
void voxelize_scatter_kernel(const float* __restrict__ vertices,
                             const int* __restrict__ facets_raw,
                             float* __restrict__ out)
{
    __shared__ float gc[VWI];   // grid coordinate table (bit-identical expr)
    if (threadIdx.x < VWI)
        gc[threadIdx.x] = (float)(2 * (int)threadIdx.x + 1 - VWI) / 96.f;  // signed
    __syncthreads();

    const int bfs = blockIdx.x;
    const int sub = bfs % SPLIT;
    const int bf  = bfs / SPLIT;
    const int b = bf / NFI;
    const int f = bf % NFI;
    const int is32 = g_facets_is_i32;

    const float* vb = vertices + b * (NVI * 3);

    float vx[4], vy[4], vz[4];
#pragma unroll
    for (int j = 0; j < 4; j++) {
        int base = (b * NFI + f) * 4 + j;           // < 16384, 32-bit safe
        int vi = is32 ? facets_raw[base] : facets_raw[base * 2];
        vx[j] = vb[vi * 3 + 0];
        vy[j] = vb[vi * 3 + 1];
        vz[j] = vb[vi * 3 + 2];
    }

    const float v3x = vx[3], v3y = vy[3], v3z = vz[3];
    const float a  = vx[0] - v3x, bb = vx[1] - v3x, c  = vx[2] - v3x;
    const float d  = vy[0] - v3y, e  = vy[1] - v3y, ff = vy[2] - v3y;
    const float g  = vz[0] - v3z, h  = vz[1] - v3z, i_ = vz[2] - v3z;

    // Adjugate rows (reference formulas)
    const float A00 = e * i_ - ff * h,  A01 = c * h - bb * i_, A02 = bb * ff - c * e;
    const float A10 = ff * g - d * i_,  A11 = a * i_ - c * g,  A12 = c * d - a * ff;
    const float A20 = d * h - e * g,    A21 = bb * g - a * h,  A22 = a * e - bb * d;
    const float det = a * (e * i_ - ff * h) - bb * (d * i_ - ff * g) + c * (d * h - e * g);
    const float inv_det = 1.0f / det;
    const float adet = fabsf(det);

    // AABB
    float xmn = fminf(fminf(vx[0], vx[1]), fminf(vx[2], vx[3]));
    float xmx = fmaxf(fmaxf(vx[0], vx[1]), fmaxf(vx[2], vx[3]));
    float ymn = fminf(fminf(vy[0], vy[1]), fminf(vy[2], vy[3]));
    float ymx = fmaxf(fmaxf(vy[0], vy[1]), fmaxf(vy[2], vy[3]));
    float zmn = fminf(fminf(vz[0], vz[1]), fminf(vz[2], vz[3]));
    float zmx = fmaxf(fmaxf(vz[0], vz[1]), fmaxf(vz[2], vz[3]));

    // k(z) = (96 z + 95)/2, ranges expanded +-1, clamped.
    int xlo = max(0,  (int)ceilf ((96.f * xmn + 95.f) * 0.5f) - 1);
    int xhi = min(95, (int)floorf((96.f * xmx + 95.f) * 0.5f) + 1);
    int ylo = max(0,  (int)ceilf ((96.f * ymn + 95.f) * 0.5f) - 1);
    int yhi = min(95, (int)floorf((96.f * ymx + 95.f) * 0.5f) + 1);
    int zloi = max(0,  (int)ceilf ((96.f * zmn + 95.f) * 0.5f) - 1);
    int zhii = min(95, (int)floorf((96.f * zmx + 95.f) * 0.5f) + 1);
    if (xlo > xhi || ylo > yhi || zloi > zhii) return;

    const int ny = yhi - ylo + 1;
    const int ncol = (xhi - xlo + 1) * ny;

    // This sub-block's column slice (ncol*SPLIT < 2^17: 32-bit safe)
    const int c0 = (ncol * sub) / SPLIT;
    const int c1 = (ncol * (sub + 1)) / SPLIT;

    // magic division by ny (col < 2^14, ny <= 96)
    const unsigned magic = (1u << 22) / (unsigned)ny + 1u;

    // n_r(z) = C_r + S_r*z; outer band [Lb - m_r, Ub + m_r] (candidates),
    // inner band [Lb + m_r, Ub - m_r] (guaranteed inside).
    const float Lb = fminf(0.f, det);
    const float Ub = fmaxf(0.f, det);
    const float tol = 1e-5f;

    const float S1 = A02, S2 = A12, S3 = A22, S4 = -(S1 + S2 + S3);
    const float inv1 = 1.f / S1, inv2 = 1.f / S2, inv3 = 1.f / S3, inv4 = 1.f / S4;
    const float ninv1 = -inv1, ninv2 = -inv2, ninv3 = -inv3, ninv4 = -inv4;
    // Conservative per-tet error scales (|dx|,|dy|,|v3z| <= 2)
    const float M1 = 2.f * (fabsf(A00) + fabsf(A01) + fabsf(A02));
    const float M2 = 2.f * (fabsf(A10) + fabsf(A11) + fabsf(A12));
    const float M3 = 2.f * (fabsf(A20) + fabsf(A21) + fabsf(A22));
    const float M4 = M1 + M2 + M3 + adet;
    const float m1 = tol * (M1 + 2.f * adet);
    const float m2 = tol * (M2 + 2.f * adet);
    const float m3 = tol * (M3 + 2.f * adet);
    const float m4 = tol * (M4 + 2.f * adet);

    // Outer pre-multiplied z-bound constants (NaN from degenerate S is dropped
    // by the fmaxf/fminf trees per column -> conservative).
    const float ZlP1 = fminf((Lb - m1) * inv1, (Ub + m1) * inv1);
    const float ZhP1 = fmaxf((Lb - m1) * inv1, (Ub + m1) * inv1);
    const float ZlP2 = fminf((Lb - m2) * inv2, (Ub + m2) * inv2);
    const float ZhP2 = fmaxf((Lb - m2) * inv2, (Ub + m2) * inv2);
    const float ZlP3 = fminf((Lb - m3) * inv3, (Ub + m3) * inv3);
    const float ZhP3 = fmaxf((Lb - m3) * inv3, (Ub + m3) * inv3);
    const float ZlP4 = fminf((Lb - m4) * inv4, (Ub + m4) * inv4);
    const float ZhP4 = fmaxf((Lb - m4) * inv4, (Ub + m4) * inv4);

    // Inner (guaranteed-inside) constants. Gate: S_r comfortably nonzero so all
    // inner arithmetic is NaN-free (infs only, which collapse to empty-inner),
    // and each shrunk band nonempty.
    const bool inner_ok =
        fabsf(S1) > 1e-30f && fabsf(S2) > 1e-30f &&
        fabsf(S3) > 1e-30f && fabsf(S4) > 1e-30f &&
        2.f * m1 < adet && 2.f * m2 < adet &&
        2.f * m3 < adet && 2.f * m4 < adet;
    const float IlP1 = fminf((Lb + m1) * inv1, (Ub - m1) * inv1);
    const float IhP1 = fmaxf((Lb + m1) * inv1, (Ub - m1) * inv1);
    const float IlP2 = fminf((Lb + m2) * inv2, (Ub - m2) * inv2);
    const float IhP2 = fmaxf((Lb + m2) * inv2, (Ub - m2) * inv2);
    const float IlP3 = fminf((Lb + m3) * inv3, (Ub - m3) * inv3);
    const float IhP3 = fmaxf((Lb + m3) * inv3, (Ub - m3) * inv3);
    const float IlP4 = fminf((Lb + m4) * inv4, (Ub - m4) * inv4);
    const float IhP4 = fmaxf((Lb + m4) * inv4, (Ub - m4) * inv4);

    for (int col = c0 + (int)threadIdx.x; col < c1; col += blockDim.x) {
        const int q = (int)(((unsigned)col * magic) >> 22);
        const int x = xlo + q;
        const int y = ylo + (col - q * ny);
        const float dx = gc[x] - v3x;
        const float dy = gc[y] - v3y;

        // Bit-exact inner-loop bases (reference op order for the z loop)
        const float base1 = fmaf(A01, dy, A00 * dx);
        const float base2 = fmaf(A11, dy, A10 * dx);
        const float base3 = fmaf(A21, dy, A20 * dx);
        // C_r = base_r - A_r2*v3z (1 ulp vs reference C; covered by slack m_r)
        const float C1 = fmaf(-A02, v3z, base1);
        const float C2 = fmaf(-A12, v3z, base2);
        const float C3 = fmaf(-A22, v3z, base3);
        const float C4 = det - C1 - C2 - C3;

        // Outer interval: one FMA per bound candidate
        const float zl1 = fmaf(C1, ninv1, ZlP1), zh1 = fmaf(C1, ninv1, ZhP1);
        const float zl2 = fmaf(C2, ninv2, ZlP2), zh2 = fmaf(C2, ninv2, ZhP2);
        const float zl3 = fmaf(C3, ninv3, ZlP3), zh3 = fmaf(C3, ninv3, ZhP3);
        const float zl4 = fmaf(C4, ninv4, ZlP4), zh4 = fmaf(C4, ninv4, ZhP4);
        const float zlo = fmaxf(fmaxf(fmaxf(zl1, zl2), fmaxf(zl3, zl4)), -2.f);
        const float zhi = fminf(fminf(fminf(zh1, zh2), fminf(zh3, zh4)),  2.f);
        if (!(zlo <= zhi)) continue;

        int klo = max(zloi, (int)ceilf ((96.f * zlo + 95.f) * 0.5f) - 1);
        int khi = min(zhii, (int)floorf((96.f * zhi + 95.f) * 0.5f) + 1);
        if (klo > khi) continue;

        // Inner guaranteed-inside interval (no expansion; clamped to [klo,khi])
        int kinlo = khi + 1, kinhi = khi;   // default: empty
        if (inner_ok) {
            const float il = fmaxf(fmaxf(fmaf(C1, ninv1, IlP1), fmaf(C2, ninv2, IlP2)),
                                   fmaxf(fmaf(C3, ninv3, IlP3), fmaf(C4, ninv4, IlP4)));
            const float ih = fminf(fminf(fmaf(C1, ninv1, IhP1), fmaf(C2, ninv2, IhP2)),
                                   fminf(fmaf(C3, ninv3, IhP3), fmaf(C4, ninv4, IhP4)));
            int ka = (int)ceilf ((96.f * il + 95.f) * 0.5f);
            int kb = (int)floorf((96.f * ih + 95.f) * 0.5f);
            ka = max(ka, klo);
            kb = min(kb, khi);
            if (ka <= kb) { kinlo = ka; kinhi = kb; }
        }

        int kfirst = 127, klast = -1;
        // Frontier below the inner interval (covers everything if inner empty)
        for (int k = klo; k < kinlo; k++) {
            const float dz = gc[k] - v3z;
            const float l1 = fmaf(A02, dz, base1) * inv_det;
            const float l2 = fmaf(A12, dz, base2) * inv_det;
            const float l3 = fmaf(A22, dz, base3) * inv_det;
            const float l4 = 1.0f - (l1 + l2 + l3);
            const float lmn = fminf(fminf(l1, l2), fminf(l3, l4));
            const float lmx = fmaxf(fmaxf(l1, l2), fmaxf(l3, l4));
            if (lmn >= 0.f && lmx <= 1.f) { kfirst = min(kfirst, k); klast = max(klast, k); }
        }
        // Frontier above the inner interval
        for (int k = kinhi + 1; k <= khi; k++) {
            const float dz = gc[k] - v3z;
            const float l1 = fmaf(A02, dz, base1) * inv_det;
            const float l2 = fmaf(A12, dz, base2) * inv_det;
            const float l3 = fmaf(A22, dz, base3) * inv_det;
            const float l4 = 1.0f - (l1 + l2 + l3);
            const float lmn = fminf(fminf(l1, l2), fminf(l3, l4));
            const float lmx = fmaxf(fmaxf(l1, l2), fmaxf(l3, l4));
            if (lmn >= 0.f && lmx <= 1.f) { kfirst = min(kfirst, k); klast = max(klast, k); }
        }
        if (kinlo <= kinhi) { kfirst = min(kfirst, kinlo); klast = max(klast, kinhi); }
        if (klast < 0) continue;

        // Inside set per column is a z-interval (convexity): run store, vectorized.
        float* orow = out + (((b * VWI + x) * VWI + y) * VWI);
        int k = kfirst;
        while (k <= klast && (k & 3)) orow[k++] = 1.0f;
        while (k + 3 <= klast) {
            *reinterpret_cast<float4*>(orow + k) = make_float4(1.f, 1.f, 1.f, 1.f);
            k += 4;
        }
        while (k <= klast) orow[k++] = 1.0f;
    }
}

extern "C" void kernel_launch(void* const* d_in, const int* in_sizes, int n_in,
                              void* d_out, int out_size)
{
    const float* vertices = (const float*)d_in[0];   // (8, 2048, 3) f32
    const int* facets_raw = (const int*)d_in[1];     // (8, 512, 4) i32/i64 (detected)
    float* out = (float*)d_out;                      // (8, 96, 96, 96) f32

    detect_facets_dtype<<<1, 256>>>(facets_raw);
    cudaMemsetAsync(d_out, 0, (size_t)out_size * sizeof(float));
    voxelize_scatter_kernel<<<BI * NFI * SPLIT, 128>>>(vertices, facets_raw, out);
}

// round 17
// speedup vs baseline: 4.1009x; 1.0380x over previous
#include <cuda_runtime.h>
#include <stdint.h>

// Voxelize_52321291600272
// B=8, NV=2048, NF=512, grid 96^3. Output float32 alpha in {0,1}.
// alpha[b,x,y,z] = 1 iff voxel center inside ANY tetrahedron (union):
// scatter of 1.0f per inside (tet,point) pair is exact and race-free.
//
// Pipeline: detect facets dtype -> per-tet constant precompute (1 thread/tet,
// 48 floats to a __device__ table) -> memset -> scatter kernel that loads the
// constants via 12 broadcast LDG.128 instead of ~230 redundant setup instrs
// per warp.
//
// Per column: outer z-interval (band +- slack) brackets candidates; inner
// z-interval (band -+ slack) is GUARANTEED inside (slack >> fp rounding of the
// reference's computed test). Only frontier voxels get the exact test.

#define VWI 96
#define NVI 2048
#define NFI 512
#define BI  8
#define SPLIT 8
#define NTETS (BI * NFI)

__device__ int g_facets_is_i32;
__device__ __align__(16) float g_tets[NTETS][48];

__global__ void detect_facets_dtype(const int* __restrict__ w)
{
    __shared__ int found;
    if (threadIdx.x == 0) found = 0;
    __syncthreads();
    // int64 LE data => every odd 32-bit word (high word of small index) is 0.
    for (int i = 2 * threadIdx.x + 1; i < 16384; i += 2 * blockDim.x) {
        if (w[i] != 0) found = 1;   // benign race
    }
    __syncthreads();
    if (threadIdx.x == 0) g_facets_is_i32 = found;
}

__global__ void precompute_tets(const float* __restrict__ vertices,
                                const int* __restrict__ facets_raw)
{
    const int t = blockIdx.x * blockDim.x + threadIdx.x;
    if (t >= NTETS) return;
    const int b = t >> 9;            // / NFI
    const int is32 = g_facets_is_i32;
    const float* vb = vertices + b * (NVI * 3);

    float vx[4], vy[4], vz[4];
#pragma unroll
    for (int j = 0; j < 4; j++) {
        int base = t * 4 + j;
        int vi = is32 ? facets_raw[base] : facets_raw[base * 2];
        vx[j] = vb[vi * 3 + 0];
        vy[j] = vb[vi * 3 + 1];
        vz[j] = vb[vi * 3 + 2];
    }

    const float v3x = vx[3], v3y = vy[3], v3z = vz[3];
    const float a  = vx[0] - v3x, bb = vx[1] - v3x, c  = vx[2] - v3x;
    const float d  = vy[0] - v3y, e  = vy[1] - v3y, ff = vy[2] - v3y;
    const float g  = vz[0] - v3z, h  = vz[1] - v3z, i_ = vz[2] - v3z;

    // Adjugate rows (reference formulas)
    const float A00 = e * i_ - ff * h,  A01 = c * h - bb * i_, A02 = bb * ff - c * e;
    const float A10 = ff * g - d * i_,  A11 = a * i_ - c * g,  A12 = c * d - a * ff;
    const float A20 = d * h - e * g,    A21 = bb * g - a * h,  A22 = a * e - bb * d;
    const float det = a * (e * i_ - ff * h) - bb * (d * i_ - ff * g) + c * (d * h - e * g);
    const float inv_det = 1.0f / det;
    const float adet = fabsf(det);

    float* o = g_tets[t];

    // AABB
    float xmn = fminf(fminf(vx[0], vx[1]), fminf(vx[2], vx[3]));
    float xmx = fmaxf(fmaxf(vx[0], vx[1]), fmaxf(vx[2], vx[3]));
    float ymn = fminf(fminf(vy[0], vy[1]), fminf(vy[2], vy[3]));
    float ymx = fmaxf(fmaxf(vy[0], vy[1]), fmaxf(vy[2], vy[3]));
    float zmn = fminf(fminf(vz[0], vz[1]), fminf(vz[2], vz[3]));
    float zmx = fmaxf(fmaxf(vz[0], vz[1]), fmaxf(vz[2], vz[3]));

    // k(z) = (96 z + 95)/2, ranges expanded +-1, clamped.
    int xlo = max(0,  (int)ceilf ((96.f * xmn + 95.f) * 0.5f) - 1);
    int xhi = min(95, (int)floorf((96.f * xmx + 95.f) * 0.5f) + 1);
    int ylo = max(0,  (int)ceilf ((96.f * ymn + 95.f) * 0.5f) - 1);
    int yhi = min(95, (int)floorf((96.f * ymx + 95.f) * 0.5f) + 1);
    int zloi = max(0,  (int)ceilf ((96.f * zmn + 95.f) * 0.5f) - 1);
    int zhii = min(95, (int)floorf((96.f * zmx + 95.f) * 0.5f) + 1);
    if (xlo > xhi || ylo > yhi || zloi > zhii) {
        o[40] = __int_as_float(0);   // ncol = 0 -> block early-exit
        return;
    }
    const int ny = yhi - ylo + 1;
    const int ncol = (xhi - xlo + 1) * ny;
    const unsigned magic = (1u << 22) / (unsigned)ny + 1u;

    // n_r(z) = C_r + S_r*z; outer band [Lb - m_r, Ub + m_r] (candidates),
    // inner band [Lb + m_r, Ub - m_r] (guaranteed inside).
    const float Lb = fminf(0.f, det);
    const float Ub = fmaxf(0.f, det);
    const float tol = 1e-5f;

    const float S1 = A02, S2 = A12, S3 = A22, S4 = -(S1 + S2 + S3);
    const float inv1 = 1.f / S1, inv2 = 1.f / S2, inv3 = 1.f / S3, inv4 = 1.f / S4;
    // Conservative per-tet error scales (|dx|,|dy|,|v3z| <= 2)
    const float M1 = 2.f * (fabsf(A00) + fabsf(A01) + fabsf(A02));
    const float M2 = 2.f * (fabsf(A10) + fabsf(A11) + fabsf(A12));
    const float M3 = 2.f * (fabsf(A20) + fabsf(A21) + fabsf(A22));
    const float M4 = M1 + M2 + M3 + adet;
    const float m1 = tol * (M1 + 2.f * adet);
    const float m2 = tol * (M2 + 2.f * adet);
    const float m3 = tol * (M3 + 2.f * adet);
    const float m4 = tol * (M4 + 2.f * adet);

    const int inner_ok =
        (fabsf(S1) > 1e-30f && fabsf(S2) > 1e-30f &&
         fabsf(S3) > 1e-30f && fabsf(S4) > 1e-30f &&
         2.f * m1 < adet && 2.f * m2 < adet &&
         2.f * m3 < adet && 2.f * m4 < adet) ? 1 : 0;

    o[0] = v3x;  o[1] = v3y;  o[2] = v3z;  o[3] = inv_det;
    o[4] = A00;  o[5] = A01;  o[6] = A02;  o[7] = -A02 * v3z;   // K1
    o[8] = A10;  o[9] = A11;  o[10] = A12; o[11] = -A12 * v3z;  // K2
    o[12] = A20; o[13] = A21; o[14] = A22; o[15] = -A22 * v3z;  // K3
    o[16] = -inv1; o[17] = -inv2; o[18] = -inv3; o[19] = -inv4;
    // Outer pre-multiplied z-bound constants (NaN from degenerate S handled
    // conservatively by fmaxf/fminf in the main kernel).
    o[20] = fminf((Lb - m1) * inv1, (Ub + m1) * inv1);
    o[21] = fminf((Lb - m2) * inv2, (Ub + m2) * inv2);
    o[22] = fminf((Lb - m3) * inv3, (Ub + m3) * inv3);
    o[23] = fminf((Lb - m4) * inv4, (Ub + m4) * inv4);
    o[24] = fmaxf((Lb - m1) * inv1, (Ub + m1) * inv1);
    o[25] = fmaxf((Lb - m2) * inv2, (Ub + m2) * inv2);
    o[26] = fmaxf((Lb - m3) * inv3, (Ub + m3) * inv3);
    o[27] = fmaxf((Lb - m4) * inv4, (Ub + m4) * inv4);
    // Inner (guaranteed-inside) constants
    o[28] = fminf((Lb + m1) * inv1, (Ub - m1) * inv1);
    o[29] = fminf((Lb + m2) * inv2, (Ub - m2) * inv2);
    o[30] = fminf((Lb + m3) * inv3, (Ub - m3) * inv3);
    o[31] = fminf((Lb + m4) * inv4, (Ub - m4) * inv4);
    o[32] = fmaxf((Lb + m1) * inv1, (Ub - m1) * inv1);
    o[33] = fmaxf((Lb + m2) * inv2, (Ub - m2) * inv2);
    o[34] = fmaxf((Lb + m3) * inv3, (Ub - m3) * inv3);
    o[35] = fmaxf((Lb + m4) * inv4, (Ub - m4) * inv4);
    o[36] = det;
    o[37] = __int_as_float(xlo);
    o[38] = __int_as_float(ylo);
    o[39] = __int_as_float(ny);
    o[40] = __int_as_float(ncol);
    o[41] = __int_as_float(zloi);
    o[42] = __int_as_float(zhii);
    o[43] = __int_as_float((int)magic);
    o[44] = __int_as_float(inner_ok);
    o[45] = 0.f; o[46] = 0.f; o[47] = 0.f;
}

__global__ __launch_bounds__(128)
void voxelize_scatter_kernel(float* __restrict__ out)
{
    __shared__ float gc[VWI];   // grid coordinate table (bit-identical expr)
    if (threadIdx.x < VWI)
        gc[threadIdx.x] = (float)(2 * (int)threadIdx.x + 1 - VWI) / 96.f;  // signed
    __syncthreads();

    const int bfs = blockIdx.x;
    const int sub = bfs & (SPLIT - 1);
    const int bf  = bfs >> 3;          // SPLIT == 8
    const int b   = bf >> 9;           // NFI == 512

    const float4* tq = reinterpret_cast<const float4*>(g_tets[bf]);
    const float4 qA = tq[10];
    const int ncol = __float_as_int(qA.x);
    if (ncol == 0) return;
    const int c0 = (ncol * sub) / SPLIT;
    const int c1 = (ncol * (sub + 1)) / SPLIT;
    if (c0 >= c1) return;

    const float4 q0 = tq[0], q1 = tq[1], q2 = tq[2], q3 = tq[3];
    const float4 q4 = tq[4], q5 = tq[5], q6 = tq[6], q7 = tq[7];
    const float4 q8 = tq[8], q9 = tq[9], qB = tq[11];

    const float v3x = q0.x, v3y = q0.y, v3z = q0.z, inv_det = q0.w;
    const float A00 = q1.x, A01 = q1.y, A02 = q1.z, K1 = q1.w;
    const float A10 = q2.x, A11 = q2.y, A12 = q2.z, K2 = q2.w;
    const float A20 = q3.x, A21 = q3.y, A22 = q3.z, K3 = q3.w;
    const float ninv1 = q4.x, ninv2 = q4.y, ninv3 = q4.z, ninv4 = q4.w;
    const float ZlP1 = q5.x, ZlP2 = q5.y, ZlP3 = q5.z, ZlP4 = q5.w;
    const float ZhP1 = q6.x, ZhP2 = q6.y, ZhP3 = q6.z, ZhP4 = q6.w;
    const float IlP1 = q7.x, IlP2 = q7.y, IlP3 = q7.z, IlP4 = q7.w;
    const float IhP1 = q8.x, IhP2 = q8.y, IhP3 = q8.z, IhP4 = q8.w;
    const float det = q9.x;
    const int xlo = __float_as_int(q9.y);
    const int ylo = __float_as_int(q9.z);
    const int ny  = __float_as_int(q9.w);
    const int zloi = __float_as_int(qA.y);
    const int zhii = __float_as_int(qA.z);
    const unsigned magic = (unsigned)__float_as_int(qA.w);
    const int inner_ok = __float_as_int(qB.x);

    for (int col = c0 + (int)threadIdx.x; col < c1; col += blockDim.x) {
        const int q = (int)(((unsigned)col * magic) >> 22);
        const int x = xlo + q;
        const int y = ylo + (col - q * ny);
        const float dx = gc[x] - v3x;
        const float dy = gc[y] - v3y;

        // Bit-exact inner-loop bases (reference op order for the z loop)
        const float base1 = fmaf(A01, dy, A00 * dx);
        const float base2 = fmaf(A11, dy, A10 * dx);
        const float base3 = fmaf(A21, dy, A20 * dx);
        // C_r = base_r + K_r (<=1 ulp vs reference C; covered by slack m_r)
        const float C1 = base1 + K1;
        const float C2 = base2 + K2;
        const float C3 = base3 + K3;
        const float C4 = det - C1 - C2 - C3;

        // Outer interval: one FMA per bound candidate
        const float zl1 = fmaf(C1, ninv1, ZlP1), zh1 = fmaf(C1, ninv1, ZhP1);
        const float zl2 = fmaf(C2, ninv2, ZlP2), zh2 = fmaf(C2, ninv2, ZhP2);
        const float zl3 = fmaf(C3, ninv3, ZlP3), zh3 = fmaf(C3, ninv3, ZhP3);
        const float zl4 = fmaf(C4, ninv4, ZlP4), zh4 = fmaf(C4, ninv4, ZhP4);
        const float zlo = fmaxf(fmaxf(fmaxf(zl1, zl2), fmaxf(zl3, zl4)), -2.f);
        const float zhi = fminf(fminf(fminf(zh1, zh2), fminf(zh3, zh4)),  2.f);
        if (!(zlo <= zhi)) continue;

        int klo = max(zloi, (int)ceilf ((96.f * zlo + 95.f) * 0.5f) - 1);
        int khi = min(zhii, (int)floorf((96.f * zhi + 95.f) * 0.5f) + 1);
        if (klo > khi) continue;

        // Inner guaranteed-inside interval (no expansion; clamped to [klo,khi])
        int kinlo = khi + 1, kinhi = khi;   // default: empty
        if (inner_ok) {
            const float il = fmaxf(fmaxf(fmaf(C1, ninv1, IlP1), fmaf(C2, ninv2, IlP2)),
                                   fmaxf(fmaf(C3, ninv3, IlP3), fmaf(C4, ninv4, IlP4)));
            const float ih = fminf(fminf(fmaf(C1, ninv1, IhP1), fmaf(C2, ninv2, IhP2)),
                                   fminf(fmaf(C3, ninv3, IhP3), fmaf(C4, ninv4, IhP4)));
            int ka = (int)ceilf ((96.f * il + 95.f) * 0.5f);
            int kb = (int)floorf((96.f * ih + 95.f) * 0.5f);
            ka = max(ka, klo);
            kb = min(kb, khi);
            if (ka <= kb) { kinlo = ka; kinhi = kb; }
        }

        int kfirst = 127, klast = -1;
        // Frontier below the inner interval (covers everything if inner empty)
        for (int k = klo; k < kinlo; k++) {
            const float dz = gc[k] - v3z;
            const float l1 = fmaf(A02, dz, base1) * inv_det;
            const float l2 = fmaf(A12, dz, base2) * inv_det;
            const float l3 = fmaf(A22, dz, base3) * inv_det;
            const float l4 = 1.0f - (l1 + l2 + l3);
            const float lmn = fminf(fminf(l1, l2), fminf(l3, l4));
            const float lmx = fmaxf(fmaxf(l1, l2), fmaxf(l3, l4));
            if (lmn >= 0.f && lmx <= 1.f) { kfirst = min(kfirst, k); klast = max(klast, k); }
        }
        // Frontier above the inner interval
        for (int k = kinhi + 1; k <= khi; k++) {
            const float dz = gc[k] - v3z;
            const float l1 = fmaf(A02, dz, base1) * inv_det;
            const float l2 = fmaf(A12, dz, base2) * inv_det;
            const float l3 = fmaf(A22, dz, base3) * inv_det;
            const float l4 = 1.0f - (l1 + l2 + l3);
            const float lmn = fminf(fminf(l1, l2), fminf(l3, l4));
            const float lmx = fmaxf(fmaxf(l1, l2), fmaxf(l3, l4));
            if (lmn >= 0.f && lmx <= 1.f) { kfirst = min(kfirst, k); klast = max(klast, k); }
        }
        if (kinlo <= kinhi) { kfirst = min(kfirst, kinlo); klast = max(klast, kinhi); }
        if (klast < 0) continue;

        // Inside set per column is a z-interval (convexity): run store, vectorized.
        float* orow = out + (((b * VWI + x) * VWI + y) * VWI);
        int k = kfirst;
        while (k <= klast && (k & 3)) orow[k++] = 1.0f;
        while (k + 3 <= klast) {
            *reinterpret_cast<float4*>(orow + k) = make_float4(1.f, 1.f, 1.f, 1.f);
            k += 4;
        }
        while (k <= klast) orow[k++] = 1.0f;
    }
}

extern "C" void kernel_launch(void* const* d_in, const int* in_sizes, int n_in,
                              void* d_out, int out_size)
{
    const float* vertices = (const float*)d_in[0];   // (8, 2048, 3) f32
    const int* facets_raw = (const int*)d_in[1];     // (8, 512, 4) i32/i64 (detected)
    float* out = (float*)d_out;                      // (8, 96, 96, 96) f32

    detect_facets_dtype<<<1, 256>>>(facets_raw);
    precompute_tets<<<(NTETS + 127) / 128, 128>>>(vertices, facets_raw);
    cudaMemsetAsync(d_out, 0, (size_t)out_size * sizeof(float));
    voxelize_scatter_kernel<<<NTETS * SPLIT, 128>>>(out);
}